// round 4
// baseline (speedup 1.0000x reference)
#include <cuda_runtime.h>
#include <math.h>

#define NV 20000
#define NF 40000
#define EE 320000
#define GG 64
#define D  256
#define D2 512

// ---------------- scratch (device globals; no allocation allowed) ----------
__device__ float g_bufF1[NF * D];
__device__ float g_bufF2[NF * D];
__device__ float g_bufV1[NV * D];
__device__ float g_bufV2[NV * D];
__device__ float g_gate[NF];
__device__ float g_gagg[GG * D];
// CSR scratch
__device__ int g_cntF[NF], g_cntV[NV];
__device__ int g_offF[NF + 1], g_offV[NV + 1];
__device__ int g_curF[NF], g_curV[NV];
__device__ int g_elF[EE], g_elV[EE];

enum { EP_NONE = 0, EP_BIAS = 1, EP_RELU_BIAS = 2, EP_RELU_BIAS_RES = 3 };

__device__ __forceinline__ unsigned f2tf(float f) {
    unsigned r;
    asm("cvt.rna.tf32.f32 %0, %1;" : "=r"(r) : "f"(f));
    return r;
}

__device__ __forceinline__ void mma_tf32(float* d, const unsigned* a,
                                         const unsigned* b, const float* c) {
    asm volatile(
        "mma.sync.aligned.m16n8k8.row.col.f32.tf32.tf32.f32 "
        "{%0,%1,%2,%3}, {%4,%5,%6,%7}, {%8,%9}, {%10,%11,%12,%13};"
        : "=f"(d[0]), "=f"(d[1]), "=f"(d[2]), "=f"(d[3])
        : "r"(a[0]), "r"(a[1]), "r"(a[2]), "r"(a[3]),
          "r"(b[0]), "r"(b[1]),
          "f"(c[0]), "f"(c[1]), "f"(c[2]), "f"(c[3]));
}

// ---- GEMM: C[M x 256] = concat-A[M x KTOT] @ W[KTOT x 256] (+epilogue) ----
// A0 covers k in [0,256); A1 covers k in [256,512) when KTOT=512.
// TF32 tensor cores, 128x128 tile, 8 warps (64x32 each), double-buffered smem.
// A tile stored in paired-k layout: pk = 8*(k>>3) + 2*(k&3) + ((k>>2)&1),
// so the fragment pair {k=c, k=c+4} is a single 64-bit LDS.
template <int MODE, int KTOT>
__global__ __launch_bounds__(256, 2)
void gemm_tc(const float* __restrict__ A0, const float* __restrict__ A1,
             const float* __restrict__ W, float* __restrict__ Cout,
             const float* __restrict__ bias, const float* __restrict__ res,
             int M)
{
    __shared__ unsigned As[2][128][18];   // [row][pk], stride 18 -> <=2-way
    __shared__ unsigned Bs[2][16][136];   // [k][n],  pad -> conflict-free

    const int tid  = threadIdx.x;
    const int wid  = tid >> 5;
    const int lane = tid & 31;
    const int g = lane >> 2;
    const int c = lane & 3;

    const int rowBase = blockIdx.y * 128;
    const int colBase = blockIdx.x * 128;
    const int wr = (wid & 1) * 64;
    const int wc = (wid >> 1) * 32;

    float acc[4][4][4];
#pragma unroll
    for (int i = 0; i < 4; i++)
#pragma unroll
        for (int j = 0; j < 4; j++)
#pragma unroll
            for (int k = 0; k < 4; k++) acc[i][j][k] = 0.f;

    float4 pa[2], pb[2];

    // prefetch helpers (load slab k0 into registers)
    auto loadSlab = [&](int k0) {
        const float* Asrc = (KTOT == 512 && k0 >= 256) ? A1 : A0;
        const int kb = k0 & 255;
#pragma unroll
        for (int i = 0; i < 2; i++) {
            const int s = tid + i * 256;
            const int r = s >> 2, kk = (s & 3) * 4;
            const int gr = rowBase + r;
            pa[i] = (gr < M)
                ? *reinterpret_cast<const float4*>(&Asrc[(size_t)gr * D + kb + kk])
                : make_float4(0.f, 0.f, 0.f, 0.f);
        }
#pragma unroll
        for (int i = 0; i < 2; i++) {
            const int s = tid + i * 256;
            const int kk2 = s >> 5, n4 = (s & 31) * 4;
            pb[i] = *reinterpret_cast<const float4*>(&W[(size_t)(k0 + kk2) * D + colBase + n4]);
        }
    };

    loadSlab(0);
    int bufId = 0;

    for (int k0 = 0; k0 < KTOT; k0 += 16) {
        // store prefetched slab into smem (convert to tf32, paired-k for A)
#pragma unroll
        for (int i = 0; i < 2; i++) {
            const int s = tid + i * 256;
            const int r = s >> 2, kk = (s & 3) * 4;
            const int pkBase = (kk & 8) + ((kk & 4) >> 2);  // k=kk+j -> pk=pkBase+2j
            As[bufId][r][pkBase + 0] = f2tf(pa[i].x);
            As[bufId][r][pkBase + 2] = f2tf(pa[i].y);
            As[bufId][r][pkBase + 4] = f2tf(pa[i].z);
            As[bufId][r][pkBase + 6] = f2tf(pa[i].w);
        }
#pragma unroll
        for (int i = 0; i < 2; i++) {
            const int s = tid + i * 256;
            const int kk2 = s >> 5, n4 = (s & 31) * 4;
            Bs[bufId][kk2][n4 + 0] = f2tf(pb[i].x);
            Bs[bufId][kk2][n4 + 1] = f2tf(pb[i].y);
            Bs[bufId][kk2][n4 + 2] = f2tf(pb[i].z);
            Bs[bufId][kk2][n4 + 3] = f2tf(pb[i].w);
        }
        __syncthreads();

        if (k0 + 16 < KTOT) loadSlab(k0 + 16);  // overlap LDG with HMMA

#pragma unroll
        for (int s8 = 0; s8 < 2; s8++) {
            const int ks = s8 * 8;
            const int pk = ks + 2 * c;   // pair {k=ks+c, k=ks+c+4}
            unsigned a[4][4], b[4][2];
#pragma unroll
            for (int mf = 0; mf < 4; mf++) {
                const int mrow = wr + mf * 16;
                const uint2 lo = *reinterpret_cast<const uint2*>(&As[bufId][mrow + g    ][pk]);
                const uint2 hi = *reinterpret_cast<const uint2*>(&As[bufId][mrow + g + 8][pk]);
                a[mf][0] = lo.x;  // k = ks+c,   row g
                a[mf][1] = hi.x;  // k = ks+c,   row g+8
                a[mf][2] = lo.y;  // k = ks+c+4, row g
                a[mf][3] = hi.y;  // k = ks+c+4, row g+8
            }
#pragma unroll
            for (int nf = 0; nf < 4; nf++) {
                const int ncol = wc + nf * 8;
                b[nf][0] = Bs[bufId][ks + c    ][ncol + g];
                b[nf][1] = Bs[bufId][ks + c + 4][ncol + g];
            }
#pragma unroll
            for (int mf = 0; mf < 4; mf++)
#pragma unroll
                for (int nf = 0; nf < 4; nf++)
                    mma_tf32(acc[mf][nf], a[mf], b[nf], acc[mf][nf]);
        }
        bufId ^= 1;
    }

#pragma unroll
    for (int mf = 0; mf < 4; mf++) {
#pragma unroll
        for (int half = 0; half < 2; half++) {
            const int r = rowBase + wr + mf * 16 + g + half * 8;
            if (r >= M) continue;
#pragma unroll
            for (int nf = 0; nf < 4; nf++) {
                const int col = colBase + wc + nf * 8 + 2 * c;
                float2 v = make_float2(acc[mf][nf][half * 2], acc[mf][nf][half * 2 + 1]);
                if (MODE == EP_BIAS) {
                    v.x += bias[col + 0];
                    v.y += bias[col + 1];
                } else if (MODE == EP_RELU_BIAS || MODE == EP_RELU_BIAS_RES) {
                    v.x = fmaxf(v.x + bias[col + 0], 0.f);
                    v.y = fmaxf(v.y + bias[col + 1], 0.f);
                    if (MODE == EP_RELU_BIAS_RES) {
                        const float2 rr = *reinterpret_cast<const float2*>(&res[(size_t)r * D + col]);
                        v.x += rr.x; v.y += rr.y;
                    }
                }
                *reinterpret_cast<float2*>(&Cout[(size_t)r * D + col]) = v;
            }
        }
    }
}

// ---------------- CSR build --------------------------------------------------
__global__ __launch_bounds__(256)
void hist_kernel(const int* __restrict__ src, const int* __restrict__ dst,
                 int* cntF, int* cntV)
{
    const int e = blockIdx.x * 256 + threadIdx.x;
    if (e >= EE) return;
    atomicAdd(&cntF[__ldg(&dst[e])], 1);
    atomicAdd(&cntV[__ldg(&src[e])], 1);
}

__global__ __launch_bounds__(1024)
void scan_excl(const int* __restrict__ cnt, int* __restrict__ off,
               int* __restrict__ cur, int n)
{
    __shared__ int wsum[32];
    __shared__ int carry;
    const int t = threadIdx.x, lane = t & 31, w = t >> 5;
    if (t == 0) carry = 0;
    __syncthreads();
    for (int base = 0; base < n; base += 1024) {
        const int i = base + t;
        const int x = (i < n) ? cnt[i] : 0;
        int incl = x;
#pragma unroll
        for (int o = 1; o < 32; o <<= 1) {
            const int v = __shfl_up_sync(0xffffffffu, incl, o);
            if (lane >= o) incl += v;
        }
        if (lane == 31) wsum[w] = incl;
        __syncthreads();
        if (w == 0) {
            const int s = wsum[lane];
            int si = s;
#pragma unroll
            for (int o = 1; o < 32; o <<= 1) {
                const int v = __shfl_up_sync(0xffffffffu, si, o);
                if (lane >= o) si += v;
            }
            wsum[lane] = si - s;  // exclusive warp offsets
        }
        __syncthreads();
        const int ex = carry + wsum[w] + incl - x;
        if (i < n) { off[i] = ex; cur[i] = ex; }
        __syncthreads();
        if (t == 1023) carry += wsum[31] + incl;
        __syncthreads();
    }
    if (t == 0) off[n] = carry;
}

__global__ __launch_bounds__(256)
void scatter_kernel(const int* __restrict__ src, const int* __restrict__ dst,
                    int* curF, int* curV, int* elF, int* elV)
{
    const int e = blockIdx.x * 256 + threadIdx.x;
    if (e >= EE) return;
    const int s = __ldg(&src[e]);
    const int d2 = __ldg(&dst[e]);
    elF[atomicAdd(&curF[d2], 1)] = s;
    elV[atomicAdd(&curV[s], 1)] = d2;
}

// ---------------- CSR gather-aggregate --------------------------------------
// out[row] = sum_{o in nbrs(row)} relu(Hself[row] + Hother[o])   (bias in Hself)
__global__ __launch_bounds__(256)
void aggregate(const float* __restrict__ Hself, const float* __restrict__ Hother,
               const int* __restrict__ off, const int* __restrict__ elist,
               float* __restrict__ out, int n)
{
    const int row = blockIdx.x * 4 + threadIdx.y;
    if (row >= n) return;
    const int d = threadIdx.x * 4;
    const float4 b = *reinterpret_cast<const float4*>(&Hself[(size_t)row * D + d]);
    float4 acc = make_float4(0.f, 0.f, 0.f, 0.f);
    int j = __ldg(&off[row]);
    const int e = __ldg(&off[row + 1]);
    for (; j + 2 <= e; j += 2) {
        const int o0 = __ldg(&elist[j]);
        const int o1 = __ldg(&elist[j + 1]);
        const float4 v0 = *reinterpret_cast<const float4*>(&Hother[(size_t)o0 * D + d]);
        const float4 v1 = *reinterpret_cast<const float4*>(&Hother[(size_t)o1 * D + d]);
        acc.x += fmaxf(b.x + v0.x, 0.f) + fmaxf(b.x + v1.x, 0.f);
        acc.y += fmaxf(b.y + v0.y, 0.f) + fmaxf(b.y + v1.y, 0.f);
        acc.z += fmaxf(b.z + v0.z, 0.f) + fmaxf(b.z + v1.z, 0.f);
        acc.w += fmaxf(b.w + v0.w, 0.f) + fmaxf(b.w + v1.w, 0.f);
    }
    if (j < e) {
        const int o0 = __ldg(&elist[j]);
        const float4 v0 = *reinterpret_cast<const float4*>(&Hother[(size_t)o0 * D + d]);
        acc.x += fmaxf(b.x + v0.x, 0.f);
        acc.y += fmaxf(b.y + v0.y, 0.f);
        acc.z += fmaxf(b.z + v0.z, 0.f);
        acc.w += fmaxf(b.w + v0.w, 0.f);
    }
    *reinterpret_cast<float4*>(&out[(size_t)row * D + d]) = acc;
}

// ---------------- attention pooling -----------------------------------------
__global__ __launch_bounds__(256)
void gate_kernel(const float* __restrict__ F, const float* __restrict__ gW,
                 const float* __restrict__ gb, float* __restrict__ gate)
{
    const int w = threadIdx.x >> 5, lane = threadIdx.x & 31;
    const int row = blockIdx.x * 8 + w;
    if (row >= NF) return;
    float s = 0.f;
#pragma unroll
    for (int i = 0; i < 8; i++) {
        const int k = lane + i * 32;
        s += F[(size_t)row * D + k] * __ldg(&gW[k]);
    }
#pragma unroll
    for (int o = 16; o > 0; o >>= 1) s += __shfl_xor_sync(0xffffffff, s, o);
    if (lane == 0) gate[row] = s + gb[0];
}

__device__ __forceinline__ int lbound(const int* __restrict__ a, int n, int v)
{
    int lo = 0, hi = n;
    while (lo < hi) {
        const int mid = (lo + hi) >> 1;
        if (a[mid] < v) lo = mid + 1; else hi = mid;
    }
    return lo;
}

__global__ __launch_bounds__(256)
void graph_agg(const float* __restrict__ gate, const float* __restrict__ T,
               const int* __restrict__ batch, float* __restrict__ gagg)
{
    __shared__ float red[256];
    __shared__ int sse[2];
    const int g = blockIdx.x, tid = threadIdx.x;
    if (tid == 0) sse[0] = lbound(batch, NF, g);
    if (tid == 1) sse[1] = lbound(batch, NF, g + 1);
    __syncthreads();
    const int s = sse[0], e = sse[1];

    float m = -INFINITY;
    for (int i = s + tid; i < e; i += 256) m = fmaxf(m, __ldg(&gate[i]));
    red[tid] = m; __syncthreads();
    for (int o = 128; o > 0; o >>= 1) {
        if (tid < o) red[tid] = fmaxf(red[tid], red[tid + o]);
        __syncthreads();
    }
    const float mm = red[0]; __syncthreads();

    float sum = 0.f;
    for (int i = s + tid; i < e; i += 256) sum += expf(__ldg(&gate[i]) - mm);
    red[tid] = sum; __syncthreads();
    for (int o = 128; o > 0; o >>= 1) {
        if (tid < o) red[tid] += red[tid + o];
        __syncthreads();
    }
    const float inv = (e > s) ? 1.f / red[0] : 0.f;

    float acc = 0.f;
    for (int i = s; i < e; i++) {
        const float alpha = expf(__ldg(&gate[i]) - mm) * inv;
        acc += alpha * T[(size_t)i * D + tid];
    }
    gagg[g * D + tid] = acc;
}

__global__ __launch_bounds__(256)
void final_g(const float* __restrict__ gagg, const float* __restrict__ glW,
             const float* __restrict__ glb, float* __restrict__ out)
{
    __shared__ float row[D];
    const int g = blockIdx.x, c = threadIdx.x;
    row[c] = gagg[g * D + c];
    __syncthreads();
    float s = glb[c];
#pragma unroll 8
    for (int k = 0; k < D; k++) s += row[k] * glW[(size_t)k * D + c];
    out[(size_t)g * D + c] = fmaxf(s, 0.f);
}

// ---------------------------------------------------------------------------
extern "C" void kernel_launch(void* const* d_in, const int* in_sizes, int n_in,
                              void* d_out, int out_size)
{
    const float* variables = (const float*)d_in[0];
    const float* factors   = (const float*)d_in[1];
    // d_in[2] = edge_attr (unused by the math)
    const int* edge_index  = (const int*)d_in[3];
    const int* batch       = (const int*)d_in[4];
    const float* mW_v2f = (const float*)d_in[5];
    const float* mb_v2f = (const float*)d_in[6];
    const float* cW_v2f = (const float*)d_in[7];
    const float* cb_v2f = (const float*)d_in[8];
    const float* mW_f2v = (const float*)d_in[9];
    const float* mb_f2v = (const float*)d_in[10];
    const float* cW_f2v = (const float*)d_in[11];
    const float* cb_f2v = (const float*)d_in[12];
    const float* gate_W = (const float*)d_in[13];
    const float* gate_b = (const float*)d_in[14];
    const float* att_W  = (const float*)d_in[15];
    const float* att_b  = (const float*)d_in[16];
    const float* gl_W   = (const float*)d_in[17];
    const float* gl_b   = (const float*)d_in[18];

    const int* src = edge_index;        // row 0: variable idx
    const int* dst = edge_index + EE;   // row 1: factor idx

    float* outV = (float*)d_out;
    float* outF = outV + (size_t)NV * D;
    float* outG = outF + (size_t)NF * D;

    float *bufF1, *bufF2, *bufV1, *bufV2, *gate, *gagg;
    int *cntF, *cntV, *offF, *offV, *curF, *curV, *elF, *elV;
    cudaGetSymbolAddress((void**)&bufF1, g_bufF1);
    cudaGetSymbolAddress((void**)&bufF2, g_bufF2);
    cudaGetSymbolAddress((void**)&bufV1, g_bufV1);
    cudaGetSymbolAddress((void**)&bufV2, g_bufV2);
    cudaGetSymbolAddress((void**)&gate,  g_gate);
    cudaGetSymbolAddress((void**)&gagg,  g_gagg);
    cudaGetSymbolAddress((void**)&cntF, g_cntF);
    cudaGetSymbolAddress((void**)&cntV, g_cntV);
    cudaGetSymbolAddress((void**)&offF, g_offF);
    cudaGetSymbolAddress((void**)&offV, g_offV);
    cudaGetSymbolAddress((void**)&curF, g_curF);
    cudaGetSymbolAddress((void**)&curV, g_curV);
    cudaGetSymbolAddress((void**)&elF,  g_elF);
    cudaGetSymbolAddress((void**)&elV,  g_elV);

    // ---- CSR build (once per launch) ----
    cudaMemsetAsync(cntF, 0, NF * sizeof(int), 0);
    cudaMemsetAsync(cntV, 0, NV * sizeof(int), 0);
    const int eb = (EE + 255) / 256;
    hist_kernel<<<eb, 256>>>(src, dst, cntF, cntV);
    scan_excl<<<1, 1024>>>(cntF, offF, curF, NF);
    scan_excl<<<1, 1024>>>(cntV, offV, curV, NV);
    scatter_kernel<<<eb, 256>>>(src, dst, curF, curV, elF, elV);

    // working copies live directly in d_out
    cudaMemcpyAsync(outV, variables, (size_t)NV * D * sizeof(float),
                    cudaMemcpyDeviceToDevice, 0);
    cudaMemcpyAsync(outF, factors, (size_t)NF * D * sizeof(float),
                    cudaMemcpyDeviceToDevice, 0);

    const dim3 gemmBlk(256);
    const dim3 gridF(2, (NF + 127) / 128);
    const dim3 gridV(2, (NV + 127) / 128);
    const dim3 aggBlk(64, 4);

    // factor/variable buffer ping-pong across layers:
    float* Fcur = outF;  float* Vcur = outV;
    float* Fnxt = bufF1; float* Vnxt = bufV1;

    for (int l = 0; l < 2; l++) {
        const float* FhBuf = (l == 0) ? bufF1 : outF;   // scratch for Fh (dead old data)
        const float* VhBuf = (l == 0) ? bufV1 : outV;

        // ---- variable -> factor ----
        {
            const float* mW = mW_v2f + (size_t)l * D2 * D;
            const float* mb = mb_v2f + (size_t)l * D;
            const float* cW = cW_v2f + (size_t)l * D2 * D;
            const float* cb = cb_v2f + (size_t)l * D;
            float* Fh = (float*)FhBuf;
            float* Vh = (l == 0) ? bufV1 : bufV2;

            gemm_tc<EP_BIAS, 256><<<gridF, gemmBlk>>>(Fcur, nullptr, mW,         Fh, mb, nullptr, NF);
            gemm_tc<EP_NONE, 256><<<gridV, gemmBlk>>>(Vcur, nullptr, mW + D * D, Vh, nullptr, nullptr, NV);
            aggregate<<<(NF + 3) / 4, aggBlk>>>(Fh, Vh, offF, elF, bufF2, NF);
            gemm_tc<EP_RELU_BIAS, 512><<<gridF, gemmBlk>>>(Fcur, bufF2, cW, Fnxt, cb, nullptr, NF);
            Fcur = Fnxt; Fnxt = (Fcur == outF) ? bufF1 : outF;
        }
        // ---- factor -> variable ----
        {
            const float* mW = mW_f2v + (size_t)l * D2 * D;
            const float* mb = mb_f2v + (size_t)l * D;
            const float* cW = cW_f2v + (size_t)l * D2 * D;
            const float* cb = cb_f2v + (size_t)l * D;
            float* Vh = (float*)VhBuf;
            float* Fh2 = bufF2;   // aggr from v2f is consumed; reuse

            gemm_tc<EP_BIAS, 256><<<gridV, gemmBlk>>>(Vcur, nullptr, mW,         Vh, mb, nullptr, NV);
            gemm_tc<EP_NONE, 256><<<gridF, gemmBlk>>>(Fcur, nullptr, mW + D * D, Fh2, nullptr, nullptr, NF);
            aggregate<<<(NV + 3) / 4, aggBlk>>>(Vh, Fh2, offV, elV, bufV2, NV);
            gemm_tc<EP_RELU_BIAS_RES, 512><<<gridV, gemmBlk>>>(Vcur, bufV2, cW, Vnxt, cb, Vcur, NV);
            Vcur = Vnxt; Vnxt = (Vcur == outV) ? bufV1 : outV;
        }
    }
    // after 2 layers: Fcur == outF, Vcur == outV (ping-pong returns)

    // ---- GlobalNode attention pooling ----
    gate_kernel<<<(NF + 7) / 8, 256>>>(outF, gate_W, gate_b, gate);
    gemm_tc<EP_BIAS, 256><<<gridF, gemmBlk>>>(outF, nullptr, att_W, bufF1, att_b, nullptr, NF);
    graph_agg<<<GG, 256>>>(gate, bufF1, batch, gagg);
    final_g<<<GG, 256>>>(gagg, gl_W, gl_b, outG);
}

// round 6
// speedup vs baseline: 1.1724x; 1.1724x over previous
#include <cuda_runtime.h>
#include <math.h>
#include <stdint.h>

#define NV 20000
#define NF 40000
#define EE 320000
#define GG 64
#define D  256
#define D2 512

// ---------------- scratch (device globals; no allocation allowed) ----------
__device__ float g_bufF1[NF * D];
__device__ float g_bufF2[NF * D];
__device__ float g_bufV1[NV * D];
__device__ float g_bufV2[NV * D];
__device__ float g_gate[NF];
__device__ float g_gagg[GG * D];
__device__ float g_wtf[1114112];     // tf32-rounded weights
// CSR scratch
__device__ int g_cntF[NF], g_cntV[NV];
__device__ int g_offF[NF + 1], g_offV[NV + 1];
__device__ int g_curF[NF], g_curV[NV];
__device__ int g_elF[EE], g_elV[EE];

enum { EP_NONE = 0, EP_BIAS = 1, EP_RELU_BIAS = 2, EP_RELU_BIAS_RES = 3 };

__device__ __forceinline__ unsigned f2tf(float f) {
    unsigned r;
    asm("cvt.rna.tf32.f32 %0, %1;" : "=r"(r) : "f"(f));
    return r;
}
__device__ __forceinline__ float roundtf(float f) {
    return __uint_as_float(f2tf(f));
}
__device__ __forceinline__ uint32_t smem_u32(const void* p) {
    uint32_t a;
    asm("{ .reg .u64 t; cvta.to.shared.u64 t, %1; cvt.u32.u64 %0, t; }"
        : "=r"(a) : "l"(p));
    return a;
}
__device__ __forceinline__ void mma_tf32(float* d, const unsigned* a,
                                         const unsigned* b, const float* c) {
    asm volatile(
        "mma.sync.aligned.m16n8k8.row.col.f32.tf32.tf32.f32 "
        "{%0,%1,%2,%3}, {%4,%5,%6,%7}, {%8,%9}, {%10,%11,%12,%13};"
        : "=f"(d[0]), "=f"(d[1]), "=f"(d[2]), "=f"(d[3])
        : "r"(a[0]), "r"(a[1]), "r"(a[2]), "r"(a[3]),
          "r"(b[0]), "r"(b[1]),
          "f"(c[0]), "f"(c[1]), "f"(c[2]), "f"(c[3]));
}

// smem layout constants (dynamic): 4-stage, As stage = 128x20 words, Bs = 16x136
#define AS_STRIDE 2560   // words per A stage
#define BS_STRIDE 2176   // words per B stage
#define BS_BASE   40960  // byte offset of B region
#define SMEM_BYTES 75776 // 4*(2560+2176)*4

// ---- GEMM body: C[128x128 tile] = concat-A[M x KTOT] @ W[KTOT x 256] ------
// Inputs MUST be tf32-rounded already (raw bits fed to mma).
template <int MODE, int KTOT>
__device__ __forceinline__ void gemm_body(
    char* smem,
    const float* __restrict__ A0, const float* __restrict__ A1,
    const float* __restrict__ W, float* __restrict__ Cout,
    const float* __restrict__ bias, const float* __restrict__ res,
    int M, int yBlk, int xBlk)
{
    unsigned* AsB = reinterpret_cast<unsigned*>(smem);
    unsigned* BsB = reinterpret_cast<unsigned*>(smem + BS_BASE);

    const int tid  = threadIdx.x;
    const int wid  = tid >> 5;
    const int lane = tid & 31;
    const int g = lane >> 2;
    const int c = lane & 3;
    const int rowBase = yBlk * 128;
    const int colBase = xBlk * 128;
    const int wr = (wid & 1) * 64;
    const int wc = (wid >> 1) * 32;

    float acc[4][4][4];
#pragma unroll
    for (int i = 0; i < 4; i++)
#pragma unroll
        for (int j = 0; j < 4; j++)
#pragma unroll
            for (int k = 0; k < 4; k++) acc[i][j][k] = 0.f;

    auto issue = [&](int slab) {
        const float* Asrc = (KTOT == 512 && slab >= 16) ? A1 : A0;
        const int kb = (slab * 16) & 255;
        unsigned* As = AsB + (slab & 3) * AS_STRIDE;
        unsigned* Bs = BsB + (slab & 3) * BS_STRIDE;
#pragma unroll
        for (int it = 0; it < 2; it++) {
            const int id = it * 256 + tid;
            const int r = id >> 2, kq = id & 3;
            const int gr = rowBase + r;
            const int grc = (gr < M) ? gr : (M - 1);
            const float* src = &Asrc[(size_t)grc * D + kb + kq * 4];
            const uint32_t dst = smem_u32(As + r * 20 + kq * 4);
            const int sz = (gr < M) ? 16 : 0;
            asm volatile("cp.async.cg.shared.global [%0], [%1], 16, %2;\n"
                         :: "r"(dst), "l"(src), "r"(sz) : "memory");
        }
#pragma unroll
        for (int it = 0; it < 2; it++) {
            const int id = it * 256 + tid;
            const int kk = id >> 5, n4 = (id & 31) * 4;
            const float* src = &W[(size_t)(slab * 16 + kk) * D + colBase + n4];
            const uint32_t dst = smem_u32(Bs + kk * 136 + n4);
            asm volatile("cp.async.cg.shared.global [%0], [%1], 16;\n"
                         :: "r"(dst), "l"(src) : "memory");
        }
        asm volatile("cp.async.commit_group;\n" ::: "memory");
    };

    constexpr int NSLAB = KTOT / 16;
    issue(0); issue(1); issue(2);

    for (int s = 0; s < NSLAB; s++) {
        asm volatile("cp.async.wait_group 2;\n" ::: "memory");
        __syncthreads();
        if (s + 3 < NSLAB) issue(s + 3);

        const unsigned* As = AsB + (s & 3) * AS_STRIDE;
        const unsigned* Bs = BsB + (s & 3) * BS_STRIDE;
#pragma unroll
        for (int ks = 0; ks < 16; ks += 8) {
            unsigned a[4][4], b[4][2];
#pragma unroll
            for (int mf = 0; mf < 4; mf++) {
                const int mrow = wr + mf * 16;
                a[mf][0] = As[(mrow + g)     * 20 + ks + c];
                a[mf][1] = As[(mrow + g + 8) * 20 + ks + c];
                a[mf][2] = As[(mrow + g)     * 20 + ks + c + 4];
                a[mf][3] = As[(mrow + g + 8) * 20 + ks + c + 4];
            }
#pragma unroll
            for (int nf = 0; nf < 4; nf++) {
                const int ncol = wc + nf * 8;
                b[nf][0] = Bs[(ks + c)     * 136 + ncol + g];
                b[nf][1] = Bs[(ks + c + 4) * 136 + ncol + g];
            }
#pragma unroll
            for (int mf = 0; mf < 4; mf++)
#pragma unroll
                for (int nf = 0; nf < 4; nf++)
                    mma_tf32(acc[mf][nf], a[mf], b[nf], acc[mf][nf]);
        }
    }

#pragma unroll
    for (int mf = 0; mf < 4; mf++) {
#pragma unroll
        for (int half = 0; half < 2; half++) {
            const int r = rowBase + wr + mf * 16 + g + half * 8;
            if (r >= M) continue;
#pragma unroll
            for (int nf = 0; nf < 4; nf++) {
                const int col = colBase + wc + nf * 8 + 2 * c;
                float2 v = make_float2(acc[mf][nf][half * 2], acc[mf][nf][half * 2 + 1]);
                if (MODE == EP_BIAS) {
                    v.x += bias[col + 0];
                    v.y += bias[col + 1];
                } else if (MODE == EP_RELU_BIAS || MODE == EP_RELU_BIAS_RES) {
                    v.x = fmaxf(v.x + bias[col + 0], 0.f);
                    v.y = fmaxf(v.y + bias[col + 1], 0.f);
                    if (MODE == EP_RELU_BIAS_RES) {
                        const float2 rr = *reinterpret_cast<const float2*>(&res[(size_t)r * D + col]);
                        v.x += rr.x; v.y += rr.y;
                    }
                    // feeds next GEMM's A: store tf32-rounded
                    v.x = roundtf(v.x);
                    v.y = roundtf(v.y);
                }
                *reinterpret_cast<float2*>(&Cout[(size_t)r * D + col]) = v;
            }
        }
    }
}

template <int MODE, int KTOT>
__global__ __launch_bounds__(256, 2)
void gemm_single(const float* __restrict__ A0, const float* __restrict__ A1,
                 const float* __restrict__ W, float* __restrict__ Cout,
                 const float* __restrict__ bias, const float* __restrict__ res,
                 int M)
{
    extern __shared__ char smem[];
    gemm_body<MODE, KTOT>(smem, A0, A1, W, Cout, bias, res, M,
                          blockIdx.y, blockIdx.x);
}

// two independent K=256 GEMMs in one grid (y-range split)
template <int MODEA, int MODEB>
__global__ __launch_bounds__(256, 2)
void gemm_dual(const float* __restrict__ Aa, const float* __restrict__ Wa,
               float* __restrict__ Ca, const float* __restrict__ biasa,
               int Ma, int nYa,
               const float* __restrict__ Ab, const float* __restrict__ Wb,
               float* __restrict__ Cb, int Mb)
{
    extern __shared__ char smem[];
    if ((int)blockIdx.y < nYa)
        gemm_body<MODEA, 256>(smem, Aa, nullptr, Wa, Ca, biasa, nullptr, Ma,
                              blockIdx.y, blockIdx.x);
    else
        gemm_body<MODEB, 256>(smem, Ab, nullptr, Wb, Cb, nullptr, nullptr, Mb,
                              blockIdx.y - nYa, blockIdx.x);
}

// ---------------- batched tf32 rounding convert ------------------------------
struct CvtArgs {
    const float* src[7];
    float* dst[7];
    int off[8];   // exclusive prefix, off[7] = total
};
__global__ __launch_bounds__(256)
void convert_multi(CvtArgs a)
{
    const int i = blockIdx.x * 256 + threadIdx.x;
    if (i >= a.off[7]) return;
    int s = 0;
    while (i >= a.off[s + 1]) s++;
    const int j = i - a.off[s];
    a.dst[s][j] = __uint_as_float(f2tf(__ldg(&a.src[s][j])));
}

// ---------------- CSR build --------------------------------------------------
__global__ __launch_bounds__(256)
void hist_kernel(const int* __restrict__ src, const int* __restrict__ dst,
                 int* cntF, int* cntV)
{
    const int e = blockIdx.x * 256 + threadIdx.x;
    if (e >= EE) return;
    atomicAdd(&cntF[__ldg(&dst[e])], 1);
    atomicAdd(&cntV[__ldg(&src[e])], 1);
}

__global__ __launch_bounds__(1024)
void scan_excl(const int* __restrict__ cnt, int* __restrict__ off,
               int* __restrict__ cur, int n)
{
    __shared__ int wsum[32];
    __shared__ int carry;
    const int t = threadIdx.x, lane = t & 31, w = t >> 5;
    if (t == 0) carry = 0;
    __syncthreads();
    for (int base = 0; base < n; base += 1024) {
        const int i = base + t;
        const int x = (i < n) ? cnt[i] : 0;
        int incl = x;
#pragma unroll
        for (int o = 1; o < 32; o <<= 1) {
            const int v = __shfl_up_sync(0xffffffffu, incl, o);
            if (lane >= o) incl += v;
        }
        if (lane == 31) wsum[w] = incl;
        __syncthreads();
        if (w == 0) {
            const int s = wsum[lane];
            int si = s;
#pragma unroll
            for (int o = 1; o < 32; o <<= 1) {
                const int v = __shfl_up_sync(0xffffffffu, si, o);
                if (lane >= o) si += v;
            }
            wsum[lane] = si - s;
        }
        __syncthreads();
        const int ex = carry + wsum[w] + incl - x;
        if (i < n) { off[i] = ex; cur[i] = ex; }
        __syncthreads();
        if (t == 1023) carry += wsum[31] + incl;
        __syncthreads();
    }
    if (t == 0) off[n] = carry;
}

__global__ __launch_bounds__(256)
void scatter_kernel(const int* __restrict__ src, const int* __restrict__ dst,
                    int* curF, int* curV, int* elF, int* elV)
{
    const int e = blockIdx.x * 256 + threadIdx.x;
    if (e >= EE) return;
    const int s = __ldg(&src[e]);
    const int d2 = __ldg(&dst[e]);
    elF[atomicAdd(&curF[d2], 1)] = s;
    elV[atomicAdd(&curV[s], 1)] = d2;
}

// ---------------- CSR gather-aggregate (output tf32-rounded) -----------------
__global__ __launch_bounds__(256)
void aggregate(const float* __restrict__ Hself, const float* __restrict__ Hother,
               const int* __restrict__ off, const int* __restrict__ elist,
               float* __restrict__ out, int n)
{
    const int row = blockIdx.x * 4 + threadIdx.y;
    if (row >= n) return;
    const int d = threadIdx.x * 4;
    const float4 b = *reinterpret_cast<const float4*>(&Hself[(size_t)row * D + d]);
    float4 acc = make_float4(0.f, 0.f, 0.f, 0.f);
    int j = __ldg(&off[row]);
    const int e = __ldg(&off[row + 1]);
    for (; j + 2 <= e; j += 2) {
        const int o0 = __ldg(&elist[j]);
        const int o1 = __ldg(&elist[j + 1]);
        const float4 v0 = *reinterpret_cast<const float4*>(&Hother[(size_t)o0 * D + d]);
        const float4 v1 = *reinterpret_cast<const float4*>(&Hother[(size_t)o1 * D + d]);
        acc.x += fmaxf(b.x + v0.x, 0.f) + fmaxf(b.x + v1.x, 0.f);
        acc.y += fmaxf(b.y + v0.y, 0.f) + fmaxf(b.y + v1.y, 0.f);
        acc.z += fmaxf(b.z + v0.z, 0.f) + fmaxf(b.z + v1.z, 0.f);
        acc.w += fmaxf(b.w + v0.w, 0.f) + fmaxf(b.w + v1.w, 0.f);
    }
    if (j < e) {
        const int o0 = __ldg(&elist[j]);
        const float4 v0 = *reinterpret_cast<const float4*>(&Hother[(size_t)o0 * D + d]);
        acc.x += fmaxf(b.x + v0.x, 0.f);
        acc.y += fmaxf(b.y + v0.y, 0.f);
        acc.z += fmaxf(b.z + v0.z, 0.f);
        acc.w += fmaxf(b.w + v0.w, 0.f);
    }
    acc.x = roundtf(acc.x); acc.y = roundtf(acc.y);
    acc.z = roundtf(acc.z); acc.w = roundtf(acc.w);
    *reinterpret_cast<float4*>(&out[(size_t)row * D + d]) = acc;
}

// ---------------- attention pooling -----------------------------------------
__global__ __launch_bounds__(256)
void gate_kernel(const float* __restrict__ F, const float* __restrict__ gW,
                 const float* __restrict__ gb, float* __restrict__ gate)
{
    const int w = threadIdx.x >> 5, lane = threadIdx.x & 31;
    const int row = blockIdx.x * 8 + w;
    if (row >= NF) return;
    float s = 0.f;
#pragma unroll
    for (int i = 0; i < 8; i++) {
        const int k = lane + i * 32;
        s += F[(size_t)row * D + k] * __ldg(&gW[k]);
    }
#pragma unroll
    for (int o = 16; o > 0; o >>= 1) s += __shfl_xor_sync(0xffffffff, s, o);
    if (lane == 0) gate[row] = s + gb[0];
}

__device__ __forceinline__ int lbound(const int* __restrict__ a, int n, int v)
{
    int lo = 0, hi = n;
    while (lo < hi) {
        const int mid = (lo + hi) >> 1;
        if (a[mid] < v) lo = mid + 1; else hi = mid;
    }
    return lo;
}

__global__ __launch_bounds__(256)
void graph_agg(const float* __restrict__ gate, const float* __restrict__ T,
               const int* __restrict__ batch, float* __restrict__ gagg)
{
    __shared__ float red[256];
    __shared__ int sse[2];
    const int g = blockIdx.x, tid = threadIdx.x;
    if (tid == 0) sse[0] = lbound(batch, NF, g);
    if (tid == 1) sse[1] = lbound(batch, NF, g + 1);
    __syncthreads();
    const int s = sse[0], e = sse[1];

    float m = -INFINITY;
    for (int i = s + tid; i < e; i += 256) m = fmaxf(m, __ldg(&gate[i]));
    red[tid] = m; __syncthreads();
    for (int o = 128; o > 0; o >>= 1) {
        if (tid < o) red[tid] = fmaxf(red[tid], red[tid + o]);
        __syncthreads();
    }
    const float mm = red[0]; __syncthreads();

    float sum = 0.f;
    for (int i = s + tid; i < e; i += 256) sum += expf(__ldg(&gate[i]) - mm);
    red[tid] = sum; __syncthreads();
    for (int o = 128; o > 0; o >>= 1) {
        if (tid < o) red[tid] += red[tid + o];
        __syncthreads();
    }
    const float inv = (e > s) ? 1.f / red[0] : 0.f;

    float acc = 0.f;
    for (int i = s; i < e; i++) {
        const float alpha = expf(__ldg(&gate[i]) - mm) * inv;
        acc += alpha * T[(size_t)i * D + tid];
    }
    gagg[g * D + tid] = acc;
}

__global__ __launch_bounds__(256)
void final_g(const float* __restrict__ gagg, const float* __restrict__ glW,
             const float* __restrict__ glb, float* __restrict__ out)
{
    __shared__ float row[D];
    const int g = blockIdx.x, c = threadIdx.x;
    row[c] = gagg[g * D + c];
    __syncthreads();
    float s = glb[c];
#pragma unroll 8
    for (int k = 0; k < D; k++) s += row[k] * glW[(size_t)k * D + c];
    out[(size_t)g * D + c] = fmaxf(s, 0.f);
}

// ---------------------------------------------------------------------------
extern "C" void kernel_launch(void* const* d_in, const int* in_sizes, int n_in,
                              void* d_out, int out_size)
{
    const float* variables = (const float*)d_in[0];
    const float* factors   = (const float*)d_in[1];
    // d_in[2] = edge_attr (unused by the math)
    const int* edge_index  = (const int*)d_in[3];
    const int* batch       = (const int*)d_in[4];
    const float* mW_v2f = (const float*)d_in[5];
    const float* mb_v2f = (const float*)d_in[6];
    const float* cW_v2f = (const float*)d_in[7];
    const float* cb_v2f = (const float*)d_in[8];
    const float* mW_f2v = (const float*)d_in[9];
    const float* mb_f2v = (const float*)d_in[10];
    const float* cW_f2v = (const float*)d_in[11];
    const float* cb_f2v = (const float*)d_in[12];
    const float* gate_W = (const float*)d_in[13];
    const float* gate_b = (const float*)d_in[14];
    const float* att_W  = (const float*)d_in[15];
    const float* att_b  = (const float*)d_in[16];
    const float* gl_W   = (const float*)d_in[17];
    const float* gl_b   = (const float*)d_in[18];

    const int* src = edge_index;        // row 0: variable idx
    const int* dst = edge_index + EE;   // row 1: factor idx

    float* outV = (float*)d_out;
    float* outF = outV + (size_t)NV * D;
    float* outG = outF + (size_t)NF * D;

    float *bufF1, *bufF2, *bufV1, *bufV2, *gate, *gagg, *wtf;
    int *cntF, *cntV, *offF, *offV, *curF, *curV, *elF, *elV;
    cudaGetSymbolAddress((void**)&bufF1, g_bufF1);
    cudaGetSymbolAddress((void**)&bufF2, g_bufF2);
    cudaGetSymbolAddress((void**)&bufV1, g_bufV1);
    cudaGetSymbolAddress((void**)&bufV2, g_bufV2);
    cudaGetSymbolAddress((void**)&gate,  g_gate);
    cudaGetSymbolAddress((void**)&gagg,  g_gagg);
    cudaGetSymbolAddress((void**)&wtf,   g_wtf);
    cudaGetSymbolAddress((void**)&cntF, g_cntF);
    cudaGetSymbolAddress((void**)&cntV, g_cntV);
    cudaGetSymbolAddress((void**)&offF, g_offF);
    cudaGetSymbolAddress((void**)&offV, g_offV);
    cudaGetSymbolAddress((void**)&curF, g_curF);
    cudaGetSymbolAddress((void**)&curV, g_curV);
    cudaGetSymbolAddress((void**)&elF,  g_elF);
    cudaGetSymbolAddress((void**)&elV,  g_elV);

    // tf32-rounded weight regions
    float* wm_v2f = wtf;                 // 2*512*256
    float* wc_v2f = wtf + 262144;
    float* wm_f2v = wtf + 524288;
    float* wc_f2v = wtf + 786432;
    float* watt   = wtf + 1048576;       // 256*256

    cudaFuncSetAttribute(gemm_single<EP_BIAS, 256>,          cudaFuncAttributeMaxDynamicSharedMemorySize, SMEM_BYTES);
    cudaFuncSetAttribute(gemm_single<EP_RELU_BIAS, 512>,     cudaFuncAttributeMaxDynamicSharedMemorySize, SMEM_BYTES);
    cudaFuncSetAttribute(gemm_single<EP_RELU_BIAS_RES, 512>, cudaFuncAttributeMaxDynamicSharedMemorySize, SMEM_BYTES);
    cudaFuncSetAttribute(gemm_dual<EP_BIAS, EP_NONE>,        cudaFuncAttributeMaxDynamicSharedMemorySize, SMEM_BYTES);

    // ---- convert inputs + weights to tf32-rounded (replaces init memcpys) ----
    {
        CvtArgs a;
        a.src[0] = variables; a.dst[0] = outV;
        a.src[1] = factors;   a.dst[1] = outF;
        a.src[2] = mW_v2f;    a.dst[2] = wm_v2f;
        a.src[3] = cW_v2f;    a.dst[3] = wc_v2f;
        a.src[4] = mW_f2v;    a.dst[4] = wm_f2v;
        a.src[5] = cW_f2v;    a.dst[5] = wc_f2v;
        a.src[6] = att_W;     a.dst[6] = watt;
        const int sz[7] = {NV * D, NF * D, 262144, 262144, 262144, 262144, 65536};
        a.off[0] = 0;
        for (int i = 0; i < 7; i++) a.off[i + 1] = a.off[i] + sz[i];
        convert_multi<<<(a.off[7] + 255) / 256, 256>>>(a);
    }

    // ---- CSR build (once per launch) ----
    cudaMemsetAsync(cntF, 0, NF * sizeof(int), 0);
    cudaMemsetAsync(cntV, 0, NV * sizeof(int), 0);
    const int eb = (EE + 255) / 256;
    hist_kernel<<<eb, 256>>>(src, dst, cntF, cntV);
    scan_excl<<<1, 1024>>>(cntF, offF, curF, NF);
    scan_excl<<<1, 1024>>>(cntV, offV, curV, NV);
    scatter_kernel<<<eb, 256>>>(src, dst, curF, curV, elF, elV);

    const dim3 gemmBlk(256);
    const int nYF = (NF + 127) / 128;   // 313
    const int nYV = (NV + 127) / 128;   // 157
    const dim3 gridF(2, nYF);
    const dim3 gridV(2, nYV);
    const dim3 gridDual(2, nYF + nYV);
    const dim3 aggBlk(64, 4);

    float* Fcur = outF;  float* Vcur = outV;
    float* Fnxt = bufF1; float* Vnxt = bufV1;

    for (int l = 0; l < 2; l++) {
        const float* FhBuf = (l == 0) ? bufF1 : outF;   // scratch (dead old data)
        const float* VhBuf = (l == 0) ? bufV1 : outV;

        // ---- variable -> factor ----
        {
            const float* mW = wm_v2f + (size_t)l * D2 * D;
            const float* mb = mb_v2f + (size_t)l * D;
            const float* cW = wc_v2f + (size_t)l * D2 * D;
            const float* cb = cb_v2f + (size_t)l * D;
            float* Fh = (float*)FhBuf;
            float* Vh = (l == 0) ? bufV1 : bufV2;

            gemm_dual<EP_BIAS, EP_NONE><<<gridDual, gemmBlk, SMEM_BYTES>>>(
                Fcur, mW, Fh, mb, NF, nYF,
                Vcur, mW + D * D, Vh, NV);
            aggregate<<<(NF + 3) / 4, aggBlk>>>(Fh, Vh, offF, elF, bufF2, NF);
            gemm_single<EP_RELU_BIAS, 512><<<gridF, gemmBlk, SMEM_BYTES>>>(
                Fcur, bufF2, cW, Fnxt, cb, nullptr, NF);
            Fcur = Fnxt; Fnxt = (Fcur == outF) ? bufF1 : outF;
        }
        // ---- factor -> variable ----
        {
            const float* mW = wm_f2v + (size_t)l * D2 * D;
            const float* mb = mb_f2v + (size_t)l * D;
            const float* cW = wc_f2v + (size_t)l * D2 * D;
            const float* cb = cb_f2v + (size_t)l * D;
            float* Vh = (float*)VhBuf;
            float* Fh2 = bufF2;

            gemm_dual<EP_BIAS, EP_NONE><<<gridDual, gemmBlk, SMEM_BYTES>>>(
                Vcur, mW, Vh, mb, NV, nYV,
                Fcur, mW + D * D, Fh2, NF);
            aggregate<<<(NV + 3) / 4, aggBlk>>>(Vh, Fh2, offV, elV, bufV2, NV);
            gemm_single<EP_RELU_BIAS_RES, 512><<<gridV, gemmBlk, SMEM_BYTES>>>(
                Vcur, bufV2, cW, Vnxt, cb, Vcur, NV);
            Vcur = Vnxt; Vnxt = (Vcur == outV) ? bufV1 : outV;
        }
    }
    // after 2 layers: Fcur == outF, Vcur == outV

    // ---- GlobalNode attention pooling ----
    gate_kernel<<<(NF + 7) / 8, 256>>>(outF, gate_W, gate_b, gate);
    gemm_single<EP_BIAS, 256><<<gridF, gemmBlk, SMEM_BYTES>>>(
        outF, nullptr, watt, bufF1, att_b, nullptr, NF);
    graph_agg<<<GG, 256>>>(gate, bufF1, batch, gagg);
    final_g<<<GG, 256>>>(gagg, gl_W, gl_b, outG);
}